// round 2
// baseline (speedup 1.0000x reference)
#include <cuda_runtime.h>
#include <math.h>
#include <stdint.h>

// Problem constants
#define Bsz  4
#define Lseq 4096
#define DIMc 1024
#define Hn   16
#define DHc  64
#define NFc  64
#define Mrows (Bsz * Lseq)          // 16384
#define BHc   (Bsz * Hn)            // 64
#define EPSf  1e-6f

// ---------------------------------------------------------------------------
// Scratch (device globals; allocation inside kernel_launch is forbidden)
// ---------------------------------------------------------------------------
__device__ float g_q[(size_t)Mrows * DIMc];
__device__ float g_k[(size_t)Mrows * DIMc];
__device__ float g_v[(size_t)Mrows * DIMc];
__device__ float g_ctx[(size_t)Mrows * DIMc];
__device__ float g_logits[(size_t)BHc * Lseq * NFc];
__device__ float g_phi[(size_t)BHc * Lseq * NFc];
__device__ float g_N[BHc * NFc * DHc];
__device__ float g_D[BHc * NFc];
__device__ float g_M[BHc];

// ---------------------------------------------------------------------------
// Helpers
// ---------------------------------------------------------------------------
__device__ __forceinline__ void atomicMaxFloat(float* addr, float val) {
    int* ai = (int*)addr;
    int old = *ai;
    while (__int_as_float(old) < val) {
        int assumed = old;
        old = atomicCAS(ai, assumed, __float_as_int(val));
        if (old == assumed) break;
    }
}

// ---------------------------------------------------------------------------
// Init: zero N/D, set M = -inf
// ---------------------------------------------------------------------------
__global__ void init_kernel() {
    int i = blockIdx.x * blockDim.x + threadIdx.x;
    if (i < BHc * NFc * DHc) g_N[i] = 0.0f;
    if (i < BHc * NFc)       g_D[i] = 0.0f;
    if (i < BHc)             g_M[i] = -1e30f;
}

// ---------------------------------------------------------------------------
// SGEMM (NT): C[M,N] = A[M,K] * W[N,K]^T + bias[N];  N = K = DIMc fixed.
// BM = BN = 128, BK = 16, 256 threads, 8x8 register micro-tile per thread.
// ---------------------------------------------------------------------------
__global__ void __launch_bounds__(256) sgemm_nt(const float* __restrict__ A,
                                                const float* __restrict__ W,
                                                const float* __restrict__ bias,
                                                float* __restrict__ C) {
    __shared__ float As[16][132];
    __shared__ float Bs[16][132];
    int t  = threadIdx.x;
    int bm = blockIdx.y * 128;
    int bn = blockIdx.x * 128;
    int tx = t & 15, ty = t >> 4;
    int lrow = t >> 2;            // 0..63
    int lcol = (t & 3) << 2;      // 0,4,8,12

    float acc[8][8];
    #pragma unroll
    for (int i = 0; i < 8; i++)
        #pragma unroll
        for (int j = 0; j < 8; j++) acc[i][j] = 0.0f;

    for (int k0 = 0; k0 < DIMc; k0 += 16) {
        #pragma unroll
        for (int r = 0; r < 2; r++) {
            int row = lrow + r * 64;
            float4 a = *(const float4*)(A + (size_t)(bm + row) * DIMc + k0 + lcol);
            As[lcol + 0][row] = a.x; As[lcol + 1][row] = a.y;
            As[lcol + 2][row] = a.z; As[lcol + 3][row] = a.w;
            float4 w = *(const float4*)(W + (size_t)(bn + row) * DIMc + k0 + lcol);
            Bs[lcol + 0][row] = w.x; Bs[lcol + 1][row] = w.y;
            Bs[lcol + 2][row] = w.z; Bs[lcol + 3][row] = w.w;
        }
        __syncthreads();
        #pragma unroll
        for (int k = 0; k < 16; k++) {
            float a[8], bb[8];
            #pragma unroll
            for (int i = 0; i < 8; i++) a[i] = As[k][ty * 8 + i];
            #pragma unroll
            for (int j = 0; j < 8; j++) bb[j] = Bs[k][tx * 8 + j];
            #pragma unroll
            for (int i = 0; i < 8; i++)
                #pragma unroll
                for (int j = 0; j < 8; j++)
                    acc[i][j] = fmaf(a[i], bb[j], acc[i][j]);
        }
        __syncthreads();
    }

    #pragma unroll
    for (int i = 0; i < 8; i++) {
        size_t row = (size_t)(bm + ty * 8 + i);
        int col = bn + tx * 8;
        #pragma unroll
        for (int j4 = 0; j4 < 2; j4++) {
            float4 o;
            o.x = acc[i][j4 * 4 + 0] + bias[col + j4 * 4 + 0];
            o.y = acc[i][j4 * 4 + 1] + bias[col + j4 * 4 + 1];
            o.z = acc[i][j4 * 4 + 2] + bias[col + j4 * 4 + 2];
            o.w = acc[i][j4 * 4 + 3] + bias[col + j4 * 4 + 3];
            *(float4*)(C + row * DIMc + col + j4 * 4) = o;
        }
    }
}

// ---------------------------------------------------------------------------
// Logits + phi kernel.
// grid: (Lseq/32, B*H), 256 threads (8 warps x 4 rows).
// logits[bh,l,f] = k . W0[:,f] - 0.5*||k||^2 ; atomicMax of block max into g_M
// phi[bh,l,f]    = softmax_f(q . W0[:,f])
// ---------------------------------------------------------------------------
__global__ void __launch_bounds__(256) logits_kernel(const float* __restrict__ Wrf) {
    int bh = blockIdx.y;
    int b = bh >> 4, h = bh & 15;
    int l0 = blockIdx.x * 32;

    __shared__ float W0s[DHc][NFc];
    __shared__ float ks[32][DHc];
    __shared__ float qs[32][DHc];
    __shared__ float wmax[8];

    int t = threadIdx.x;
    for (int e = t; e < DHc * NFc; e += 256)
        W0s[e / NFc][e % NFc] = Wrf[h * DHc * NFc + e];
    for (int e = t; e < 32 * DHc; e += 256) {
        int row = e >> 6, d = e & 63;
        size_t g = (size_t)(b * Lseq + l0 + row) * DIMc + h * DHc + d;
        ks[row][d] = g_k[g];
        qs[row][d] = g_q[g];
    }
    __syncthreads();

    int warp = t >> 5, lane = t & 31;
    float lmax = -1e30f;

    #pragma unroll 1
    for (int r = 0; r < 4; r++) {
        int l = warp * 4 + r;
        float aK0 = 0.f, aK1 = 0.f, aQ0 = 0.f, aQ1 = 0.f, kk = 0.f;
        #pragma unroll
        for (int d = 0; d < DHc; d++) {
            float kv = ks[l][d], qv = qs[l][d];
            float w0 = W0s[d][lane], w1 = W0s[d][lane + 32];
            aK0 = fmaf(kv, w0, aK0); aK1 = fmaf(kv, w1, aK1);
            aQ0 = fmaf(qv, w0, aQ0); aQ1 = fmaf(qv, w1, aQ1);
            kk  = fmaf(kv, kv, kk);
        }
        float lg0 = aK0 - 0.5f * kk;
        float lg1 = aK1 - 0.5f * kk;
        lmax = fmaxf(lmax, fmaxf(lg0, lg1));
        size_t base = ((size_t)bh * Lseq + l0 + l) * NFc;
        g_logits[base + lane]      = lg0;
        g_logits[base + lane + 32] = lg1;

        // per-position softmax over 64 features (warp-collective)
        float pm = fmaxf(aQ0, aQ1);
        #pragma unroll
        for (int o = 16; o > 0; o >>= 1)
            pm = fmaxf(pm, __shfl_xor_sync(0xffffffffu, pm, o));
        float e0 = __expf(aQ0 - pm), e1 = __expf(aQ1 - pm);
        float s = e0 + e1;
        #pragma unroll
        for (int o = 16; o > 0; o >>= 1)
            s += __shfl_xor_sync(0xffffffffu, s, o);
        float inv = 1.0f / s;
        g_phi[base + lane]      = e0 * inv;
        g_phi[base + lane + 32] = e1 * inv;
    }

    #pragma unroll
    for (int o = 16; o > 0; o >>= 1)
        lmax = fmaxf(lmax, __shfl_xor_sync(0xffffffffu, lmax, o));
    if (lane == 0) wmax[warp] = lmax;
    __syncthreads();
    if (t == 0) {
        float m = wmax[0];
        #pragma unroll
        for (int i = 1; i < 8; i++) m = fmaxf(m, wmax[i]);
        atomicMaxFloat(&g_M[bh], m);
    }
}

// ---------------------------------------------------------------------------
// N/D accumulation: per (b,h) chunk of 256 L rows,
//   Npart[f,d] = sum_l exp(logit[l,f]-m) * v[l,d], Dpart[f] = sum_l exp(...)
// grid: (Lseq/256, B*H), 256 threads, 4x4 micro-tile per thread over (f,d).
// ---------------------------------------------------------------------------
__global__ void __launch_bounds__(256) nd_kernel() {
    int bh = blockIdx.y;
    int b = bh >> 4, h = bh & 15;
    int l0 = blockIdx.x * 256;

    __shared__ float Es[16][NFc];
    __shared__ float Vs[16][DHc];

    int t = threadIdx.x;
    float m = g_M[bh];
    int tf = (t >> 4) << 2;   // 0..60  (feature group)
    int td = (t & 15) << 2;   // 0..60  (dh group)
    int lrow = t >> 4;        // 0..15 (loader row)
    int lc4  = (t & 15) << 2; // 0..60 (loader col group)

    float acc[4][4];
    #pragma unroll
    for (int i = 0; i < 4; i++)
        #pragma unroll
        for (int j = 0; j < 4; j++) acc[i][j] = 0.0f;
    float dacc[4] = {0.f, 0.f, 0.f, 0.f};

    for (int lt = 0; lt < 256; lt += 16) {
        int l = l0 + lt + lrow;
        float4 lg = *(const float4*)&g_logits[((size_t)bh * Lseq + l) * NFc + lc4];
        Es[lrow][lc4 + 0] = __expf(lg.x - m);
        Es[lrow][lc4 + 1] = __expf(lg.y - m);
        Es[lrow][lc4 + 2] = __expf(lg.z - m);
        Es[lrow][lc4 + 3] = __expf(lg.w - m);
        float4 vv = *(const float4*)&g_v[(size_t)(b * Lseq + l) * DIMc + h * DHc + lc4];
        Vs[lrow][lc4 + 0] = vv.x; Vs[lrow][lc4 + 1] = vv.y;
        Vs[lrow][lc4 + 2] = vv.z; Vs[lrow][lc4 + 3] = vv.w;
        __syncthreads();
        #pragma unroll
        for (int kk = 0; kk < 16; kk++) {
            float a[4], bb[4];
            #pragma unroll
            for (int i = 0; i < 4; i++) a[i]  = Es[kk][tf + i];
            #pragma unroll
            for (int j = 0; j < 4; j++) bb[j] = Vs[kk][td + j];
            #pragma unroll
            for (int i = 0; i < 4; i++)
                #pragma unroll
                for (int j = 0; j < 4; j++)
                    acc[i][j] = fmaf(a[i], bb[j], acc[i][j]);
            if (td == 0) {
                #pragma unroll
                for (int i = 0; i < 4; i++) dacc[i] += a[i];
            }
        }
        __syncthreads();
    }

    #pragma unroll
    for (int i = 0; i < 4; i++)
        #pragma unroll
        for (int j = 0; j < 4; j++)
            atomicAdd(&g_N[(size_t)bh * NFc * DHc + (tf + i) * DHc + td + j], acc[i][j]);
    if (td == 0) {
        #pragma unroll
        for (int i = 0; i < 4; i++)
            atomicAdd(&g_D[bh * NFc + tf + i], dacc[i]);
    }
}

// ---------------------------------------------------------------------------
// Combine: ctx[b,l,h*64+d] = (phi . N[:,d]) / (phi . D + S*EPS)
// grid: (Lseq/64, B*H), 256 threads (8 warps x 8 rows each).
// ---------------------------------------------------------------------------
__global__ void __launch_bounds__(256) combine_kernel() {
    int bh = blockIdx.y;
    int b = bh >> 4, h = bh & 15;
    int l0 = blockIdx.x * 64;

    __shared__ float Ns[NFc][DHc];
    __shared__ float Ds[NFc];
    __shared__ float sSE;

    int t = threadIdx.x;
    for (int e = t; e < NFc * DHc; e += 256)
        Ns[e / DHc][e % DHc] = g_N[(size_t)bh * NFc * DHc + e];
    if (t < NFc) Ds[t] = g_D[bh * NFc + t];
    __syncthreads();
    if (t == 0) {
        float s = 0.f;
        #pragma unroll
        for (int f = 0; f < NFc; f++) s += Ds[f];
        sSE = s * EPSf;
    }
    __syncthreads();

    int warp = t >> 5, lane = t & 31;
    #pragma unroll 1
    for (int r = 0; r < 8; r++) {
        int l = l0 + warp * 8 + r;
        const float* prow = &g_phi[((size_t)bh * Lseq + l) * NFc];
        float num0 = 0.f, num1 = 0.f, den = 0.f;
        #pragma unroll
        for (int f = 0; f < NFc; f++) {
            float p = prow[f];
            num0 = fmaf(p, Ns[f][lane], num0);
            num1 = fmaf(p, Ns[f][lane + 32], num1);
            den  = fmaf(p, Ds[f], den);
        }
        float invd = 1.0f / (den + sSE);
        size_t g = (size_t)(b * Lseq + l) * DIMc + h * DHc;
        g_ctx[g + lane]      = num0 * invd;
        g_ctx[g + lane + 32] = num1 * invd;
    }
}

// ---------------------------------------------------------------------------
// Launch
// ---------------------------------------------------------------------------
extern "C" void kernel_launch(void* const* d_in, const int* in_sizes, int n_in,
                              void* d_out, int out_size) {
    const float* x   = (const float*)d_in[0];
    const float* Wq  = (const float*)d_in[1];
    const float* bq  = (const float*)d_in[2];
    const float* Wk  = (const float*)d_in[3];
    const float* bk  = (const float*)d_in[4];
    const float* Wv  = (const float*)d_in[5];
    const float* bv  = (const float*)d_in[6];
    const float* Wo  = (const float*)d_in[7];
    const float* bo  = (const float*)d_in[8];
    const float* Wrf = (const float*)d_in[9];
    float* out = (float*)d_out;

    float *q, *k, *v, *ctx;
    cudaGetSymbolAddress((void**)&q,   g_q);
    cudaGetSymbolAddress((void**)&k,   g_k);
    cudaGetSymbolAddress((void**)&v,   g_v);
    cudaGetSymbolAddress((void**)&ctx, g_ctx);

    init_kernel<<<(BHc * NFc * DHc + 255) / 256, 256>>>();

    dim3 gg(DIMc / 128, Mrows / 128);
    sgemm_nt<<<gg, 256>>>(x, Wq, bq, q);
    sgemm_nt<<<gg, 256>>>(x, Wk, bk, k);
    sgemm_nt<<<gg, 256>>>(x, Wv, bv, v);

    logits_kernel<<<dim3(Lseq / 32, BHc), 256>>>(Wrf);
    nd_kernel<<<dim3(Lseq / 256, BHc), 256>>>();
    combine_kernel<<<dim3(Lseq / 64, BHc), 256>>>();

    sgemm_nt<<<gg, 256>>>(ctx, Wo, bo, out);
}

// round 4
// speedup vs baseline: 1.6927x; 1.6927x over previous
#include <cuda_runtime.h>
#include <cuda_bf16.h>
#include <math.h>
#include <stdint.h>

// Problem constants
#define Bsz  4
#define Lseq 4096
#define DIMc 1024
#define Hn   16
#define DHc  64
#define NFc  64
#define Mrows (Bsz * Lseq)          // 16384
#define BHc   (Bsz * Hn)            // 64
#define EPSf  1e-6f

// ---------------------------------------------------------------------------
// Scratch (device globals)
// ---------------------------------------------------------------------------
__device__ float g_q[(size_t)Mrows * DIMc];
__device__ float g_k[(size_t)Mrows * DIMc];
__device__ float g_v[(size_t)Mrows * DIMc];
__device__ float g_logits[(size_t)BHc * Lseq * NFc];
__device__ float g_phi[(size_t)BHc * Lseq * NFc];
__device__ float g_N[BHc * NFc * DHc];
__device__ float g_D[BHc * NFc];
__device__ float g_M[BHc];

// bf16 split buffers
__device__ __nv_bfloat16 g_xhi[(size_t)Mrows * DIMc];
__device__ __nv_bfloat16 g_xlo[(size_t)Mrows * DIMc];
__device__ __nv_bfloat16 g_whi[4 * DIMc * DIMc];
__device__ __nv_bfloat16 g_wlo[4 * DIMc * DIMc];
__device__ __nv_bfloat16 g_chi[(size_t)Mrows * DIMc];
__device__ __nv_bfloat16 g_clo[(size_t)Mrows * DIMc];

// ---------------------------------------------------------------------------
// PTX helpers (all non-'a'-gated: mma.sync / ldmatrix / cp.async)
// ---------------------------------------------------------------------------
__device__ __forceinline__ uint32_t smem_u32(const void* p) {
    uint32_t a;
    asm("{ .reg .u64 t; cvta.to.shared.u64 t, %1; cvt.u32.u64 %0, t; }" : "=r"(a) : "l"(p));
    return a;
}

#define CP16(dst, src) \
    asm volatile("cp.async.cg.shared.global [%0], [%1], 16;" :: "r"(dst), "l"(src))
#define CP_COMMIT() asm volatile("cp.async.commit_group;" ::: "memory")
#define CP_WAIT(n)  asm volatile("cp.async.wait_group %0;" :: "n"(n) : "memory")

__device__ __forceinline__ void ldsm_x4(uint32_t* r, uint32_t addr) {
    asm volatile("ldmatrix.sync.aligned.m8n8.x4.shared.b16 {%0,%1,%2,%3}, [%4];"
        : "=r"(r[0]), "=r"(r[1]), "=r"(r[2]), "=r"(r[3]) : "r"(addr));
}
__device__ __forceinline__ void ldsm_x2(uint32_t* r, uint32_t addr) {
    asm volatile("ldmatrix.sync.aligned.m8n8.x2.shared.b16 {%0,%1}, [%2];"
        : "=r"(r[0]), "=r"(r[1]) : "r"(addr));
}
__device__ __forceinline__ void mma16816(float* c, const uint32_t* a, const uint32_t* b) {
    asm volatile(
        "mma.sync.aligned.m16n8k16.row.col.f32.bf16.bf16.f32 "
        "{%0,%1,%2,%3}, {%4,%5,%6,%7}, {%8,%9}, {%0,%1,%2,%3};"
        : "+f"(c[0]), "+f"(c[1]), "+f"(c[2]), "+f"(c[3])
        : "r"(a[0]), "r"(a[1]), "r"(a[2]), "r"(a[3]), "r"(b[0]), "r"(b[1]));
}

// SMEM tile geometry: bf16 rows of 32 elems padded to 40 (80 bytes) -> ldmatrix
// octets hit banks {0,20,8,28,16,4,24,12}: conflict-free.
#define ROWB       80
#define MAT_BYTES  (128 * ROWB)      // 10240
#define STG_BYTES  (4 * MAT_BYTES)   // 40960 : Ahi | Alo | Bhi | Blo
#define NSTAGE     3
#define GEMM_SMEM  (512 + NSTAGE * STG_BYTES)
#define OFF_AHI 0
#define OFF_ALO MAT_BYTES
#define OFF_BHI (2 * MAT_BYTES)
#define OFF_BLO (3 * MAT_BYTES)

// ---------------------------------------------------------------------------
// Helpers
// ---------------------------------------------------------------------------
__device__ __forceinline__ void atomicMaxFloat(float* addr, float val) {
    int* ai = (int*)addr;
    int old = *ai;
    while (__int_as_float(old) < val) {
        int assumed = old;
        old = atomicCAS(ai, assumed, __float_as_int(val));
        if (old == assumed) break;
    }
}

// ---------------------------------------------------------------------------
// fp32 -> bf16 hi/lo split
// ---------------------------------------------------------------------------
__global__ void split_kernel(const float* __restrict__ src,
                             __nv_bfloat16* __restrict__ hi,
                             __nv_bfloat16* __restrict__ lo, int n4) {
    int i = blockIdx.x * blockDim.x + threadIdx.x;
    if (i >= n4) return;
    float4 v = ((const float4*)src)[i];
    __nv_bfloat16 h[4], l[4];
    h[0] = __float2bfloat16(v.x); l[0] = __float2bfloat16(v.x - __bfloat162float(h[0]));
    h[1] = __float2bfloat16(v.y); l[1] = __float2bfloat16(v.y - __bfloat162float(h[1]));
    h[2] = __float2bfloat16(v.z); l[2] = __float2bfloat16(v.z - __bfloat162float(h[2]));
    h[3] = __float2bfloat16(v.w); l[3] = __float2bfloat16(v.w - __bfloat162float(h[3]));
    ((uint2*)hi)[i] = *(uint2*)h;
    ((uint2*)lo)[i] = *(uint2*)l;
}

// ---------------------------------------------------------------------------
// Init
// ---------------------------------------------------------------------------
__global__ void init_kernel() {
    int i = blockIdx.x * blockDim.x + threadIdx.x;
    if (i < BHc * NFc * DHc) g_N[i] = 0.0f;
    if (i < BHc * NFc)       g_D[i] = 0.0f;
    if (i < BHc)             g_M[i] = -1e30f;
}

// ---------------------------------------------------------------------------
// HMMA bf16-split GEMM: C[M,1024] = (Ahi+Alo)(Whi+Wlo)^T + bias
// 128x128 tile, BK=32, 3-stage cp.async pipeline, 8 warps (2x4), 64x32/warp.
// ---------------------------------------------------------------------------
__device__ __forceinline__ void issue_chunk(
    uint32_t sbase, int t,
    const __nv_bfloat16* __restrict__ Ahi, const __nv_bfloat16* __restrict__ Alo,
    const __nv_bfloat16* __restrict__ Whi, const __nv_bfloat16* __restrict__ Wlo,
    int bm, int bn, int kOff)
{
    #pragma unroll
    for (int j = 0; j < 2; j++) {
        int idx = t + j * 256;
        int r = idx >> 2, c = idx & 3;
        uint32_t so = (uint32_t)(r * ROWB + c * 16);
        size_t ga = (size_t)(bm + r) * DIMc + kOff + c * 8;
        size_t gb = (size_t)(bn + r) * DIMc + kOff + c * 8;
        CP16(sbase + OFF_AHI + so, Ahi + ga);
        CP16(sbase + OFF_ALO + so, Alo + ga);
        CP16(sbase + OFF_BHI + so, Whi + gb);
        CP16(sbase + OFF_BLO + so, Wlo + gb);
    }
    CP_COMMIT();
}

__global__ void __launch_bounds__(256, 1) gemm_split(
    const __nv_bfloat16* __restrict__ Ahi, const __nv_bfloat16* __restrict__ Alo,
    const __nv_bfloat16* __restrict__ Whi, const __nv_bfloat16* __restrict__ Wlo,
    const float* __restrict__ bias, float* __restrict__ C)
{
    extern __shared__ __align__(16) char sm[];
    float* sbias = (float*)sm;
    uint32_t sb = smem_u32(sm) + 512;

    int t = threadIdx.x;
    int wid = t >> 5, lane = t & 31;
    int warp_m = wid >> 2, warp_n = wid & 3;
    int bm = blockIdx.y << 7;
    int bn = blockIdx.x << 7;

    if (t < 128) sbias[t] = bias[bn + t];

    float acc[4][4][4];
    #pragma unroll
    for (int mi = 0; mi < 4; mi++)
        #pragma unroll
        for (int ni = 0; ni < 4; ni++)
            #pragma unroll
            for (int e = 0; e < 4; e++) acc[mi][ni][e] = 0.0f;

    // lane-derived smem offsets (bytes, relative to stage base)
    uint32_t aoff = (uint32_t)((warp_m * 64 + (lane & 15)) * ROWB + (lane >> 4) * 16);
    uint32_t boff = (uint32_t)((warp_n * 32 + (lane & 7)) * ROWB + ((lane >> 3) & 1) * 16);

    // prologue: stages 0,1
    issue_chunk(sb + 0 * STG_BYTES, t, Ahi, Alo, Whi, Wlo, bm, bn, 0);
    issue_chunk(sb + 1 * STG_BYTES, t, Ahi, Alo, Whi, Wlo, bm, bn, 32);

    #pragma unroll 1
    for (int ch = 0; ch < 32; ch++) {
        CP_WAIT(1);
        __syncthreads();
        if (ch + 2 < 32)
            issue_chunk(sb + ((ch + 2) % NSTAGE) * STG_BYTES, t,
                        Ahi, Alo, Whi, Wlo, bm, bn, (ch + 2) * 32);
        uint32_t stg = sb + (ch % NSTAGE) * STG_BYTES;
        #pragma unroll
        for (int ks = 0; ks < 2; ks++) {
            uint32_t ahi[4][4], alo[4][4], bhi[4][2], blo[4][2];
            #pragma unroll
            for (int mi = 0; mi < 4; mi++) {
                uint32_t a = stg + aoff + (uint32_t)(mi * 16 * ROWB + ks * 32);
                ldsm_x4(ahi[mi], a + OFF_AHI);
                ldsm_x4(alo[mi], a + OFF_ALO);
            }
            #pragma unroll
            for (int ni = 0; ni < 4; ni++) {
                uint32_t b = stg + boff + (uint32_t)(ni * 8 * ROWB + ks * 32);
                ldsm_x2(bhi[ni], b + OFF_BHI);
                ldsm_x2(blo[ni], b + OFF_BLO);
            }
            #pragma unroll
            for (int mi = 0; mi < 4; mi++)
                #pragma unroll
                for (int ni = 0; ni < 4; ni++) {
                    mma16816(acc[mi][ni], ahi[mi], bhi[ni]);
                    mma16816(acc[mi][ni], ahi[mi], blo[ni]);
                    mma16816(acc[mi][ni], alo[mi], bhi[ni]);
                }
        }
        __syncthreads();
    }

    // epilogue
    #pragma unroll
    for (int mi = 0; mi < 4; mi++) {
        int row0 = bm + warp_m * 64 + mi * 16 + (lane >> 2);
        #pragma unroll
        for (int ni = 0; ni < 4; ni++) {
            int col = warp_n * 32 + ni * 8 + (lane & 3) * 2;
            float b0 = sbias[col], b1 = sbias[col + 1];
            float2 o0 = make_float2(acc[mi][ni][0] + b0, acc[mi][ni][1] + b1);
            float2 o1 = make_float2(acc[mi][ni][2] + b0, acc[mi][ni][3] + b1);
            *(float2*)(C + (size_t)row0 * DIMc + bn + col) = o0;
            *(float2*)(C + (size_t)(row0 + 8) * DIMc + bn + col) = o1;
        }
    }
}

// ---------------------------------------------------------------------------
// Logits + phi kernel.
// ---------------------------------------------------------------------------
__global__ void __launch_bounds__(256) logits_kernel(const float* __restrict__ Wrf) {
    int bh = blockIdx.y;
    int b = bh >> 4, h = bh & 15;
    int l0 = blockIdx.x * 32;

    __shared__ float W0s[DHc][NFc];
    __shared__ float ks[32][DHc];
    __shared__ float qs[32][DHc];
    __shared__ float wmax[8];

    int t = threadIdx.x;
    for (int e = t; e < DHc * NFc; e += 256)
        W0s[e / NFc][e % NFc] = Wrf[h * DHc * NFc + e];
    for (int e = t; e < 32 * DHc; e += 256) {
        int row = e >> 6, d = e & 63;
        size_t g = (size_t)(b * Lseq + l0 + row) * DIMc + h * DHc + d;
        ks[row][d] = g_k[g];
        qs[row][d] = g_q[g];
    }
    __syncthreads();

    int warp = t >> 5, lane = t & 31;
    float lmax = -1e30f;

    #pragma unroll 1
    for (int r = 0; r < 4; r++) {
        int l = warp * 4 + r;
        float aK0 = 0.f, aK1 = 0.f, aQ0 = 0.f, aQ1 = 0.f, kk = 0.f;
        #pragma unroll
        for (int d = 0; d < DHc; d++) {
            float kv = ks[l][d], qv = qs[l][d];
            float w0 = W0s[d][lane], w1 = W0s[d][lane + 32];
            aK0 = fmaf(kv, w0, aK0); aK1 = fmaf(kv, w1, aK1);
            aQ0 = fmaf(qv, w0, aQ0); aQ1 = fmaf(qv, w1, aQ1);
            kk  = fmaf(kv, kv, kk);
        }
        float lg0 = aK0 - 0.5f * kk;
        float lg1 = aK1 - 0.5f * kk;
        lmax = fmaxf(lmax, fmaxf(lg0, lg1));
        size_t base = ((size_t)bh * Lseq + l0 + l) * NFc;
        g_logits[base + lane]      = lg0;
        g_logits[base + lane + 32] = lg1;

        float pm = fmaxf(aQ0, aQ1);
        #pragma unroll
        for (int o = 16; o > 0; o >>= 1)
            pm = fmaxf(pm, __shfl_xor_sync(0xffffffffu, pm, o));
        float e0 = __expf(aQ0 - pm), e1 = __expf(aQ1 - pm);
        float s = e0 + e1;
        #pragma unroll
        for (int o = 16; o > 0; o >>= 1)
            s += __shfl_xor_sync(0xffffffffu, s, o);
        float inv = 1.0f / s;
        g_phi[base + lane]      = e0 * inv;
        g_phi[base + lane + 32] = e1 * inv;
    }

    #pragma unroll
    for (int o = 16; o > 0; o >>= 1)
        lmax = fmaxf(lmax, __shfl_xor_sync(0xffffffffu, lmax, o));
    if (lane == 0) wmax[warp] = lmax;
    __syncthreads();
    if (t == 0) {
        float m = wmax[0];
        #pragma unroll
        for (int i = 1; i < 8; i++) m = fmaxf(m, wmax[i]);
        atomicMaxFloat(&g_M[bh], m);
    }
}

// ---------------------------------------------------------------------------
// N/D accumulation
// ---------------------------------------------------------------------------
__global__ void __launch_bounds__(256) nd_kernel() {
    int bh = blockIdx.y;
    int b = bh >> 4, h = bh & 15;
    int l0 = blockIdx.x * 256;

    __shared__ float Es[16][NFc];
    __shared__ float Vs[16][DHc];

    int t = threadIdx.x;
    float m = g_M[bh];
    int tf = (t >> 4) << 2;
    int td = (t & 15) << 2;
    int lrow = t >> 4;
    int lc4  = (t & 15) << 2;

    float acc[4][4];
    #pragma unroll
    for (int i = 0; i < 4; i++)
        #pragma unroll
        for (int j = 0; j < 4; j++) acc[i][j] = 0.0f;
    float dacc[4] = {0.f, 0.f, 0.f, 0.f};

    for (int lt = 0; lt < 256; lt += 16) {
        int l = l0 + lt + lrow;
        float4 lg = *(const float4*)&g_logits[((size_t)bh * Lseq + l) * NFc + lc4];
        Es[lrow][lc4 + 0] = __expf(lg.x - m);
        Es[lrow][lc4 + 1] = __expf(lg.y - m);
        Es[lrow][lc4 + 2] = __expf(lg.z - m);
        Es[lrow][lc4 + 3] = __expf(lg.w - m);
        float4 vv = *(const float4*)&g_v[(size_t)(b * Lseq + l) * DIMc + h * DHc + lc4];
        Vs[lrow][lc4 + 0] = vv.x; Vs[lrow][lc4 + 1] = vv.y;
        Vs[lrow][lc4 + 2] = vv.z; Vs[lrow][lc4 + 3] = vv.w;
        __syncthreads();
        #pragma unroll
        for (int kk = 0; kk < 16; kk++) {
            float a[4], bb[4];
            #pragma unroll
            for (int i = 0; i < 4; i++) a[i]  = Es[kk][tf + i];
            #pragma unroll
            for (int j = 0; j < 4; j++) bb[j] = Vs[kk][td + j];
            #pragma unroll
            for (int i = 0; i < 4; i++)
                #pragma unroll
                for (int j = 0; j < 4; j++)
                    acc[i][j] = fmaf(a[i], bb[j], acc[i][j]);
            if (td == 0) {
                #pragma unroll
                for (int i = 0; i < 4; i++) dacc[i] += a[i];
            }
        }
        __syncthreads();
    }

    #pragma unroll
    for (int i = 0; i < 4; i++)
        #pragma unroll
        for (int j = 0; j < 4; j++)
            atomicAdd(&g_N[(size_t)bh * NFc * DHc + (tf + i) * DHc + td + j], acc[i][j]);
    if (td == 0) {
        #pragma unroll
        for (int i = 0; i < 4; i++)
            atomicAdd(&g_D[bh * NFc + tf + i], dacc[i]);
    }
}

// ---------------------------------------------------------------------------
// Combine: writes bf16 hi/lo of ctx (consumed by the HMMA out-GEMM)
// ---------------------------------------------------------------------------
__global__ void __launch_bounds__(256) combine_kernel() {
    int bh = blockIdx.y;
    int b = bh >> 4, h = bh & 15;
    int l0 = blockIdx.x * 64;

    __shared__ float Ns[NFc][DHc];
    __shared__ float Ds[NFc];
    __shared__ float sSE;

    int t = threadIdx.x;
    for (int e = t; e < NFc * DHc; e += 256)
        Ns[e / DHc][e % DHc] = g_N[(size_t)bh * NFc * DHc + e];
    if (t < NFc) Ds[t] = g_D[bh * NFc + t];
    __syncthreads();
    if (t == 0) {
        float s = 0.f;
        #pragma unroll
        for (int f = 0; f < NFc; f++) s += Ds[f];
        sSE = s * EPSf;
    }
    __syncthreads();

    int warp = t >> 5, lane = t & 31;
    #pragma unroll 1
    for (int r = 0; r < 8; r++) {
        int l = l0 + warp * 8 + r;
        const float* prow = &g_phi[((size_t)bh * Lseq + l) * NFc];
        float num0 = 0.f, num1 = 0.f, den = 0.f;
        #pragma unroll
        for (int f = 0; f < NFc; f++) {
            float p = prow[f];
            num0 = fmaf(p, Ns[f][lane], num0);
            num1 = fmaf(p, Ns[f][lane + 32], num1);
            den  = fmaf(p, Ds[f], den);
        }
        float invd = 1.0f / (den + sSE);
        float v0 = num0 * invd;
        float v1 = num1 * invd;
        size_t g = (size_t)(b * Lseq + l) * DIMc + h * DHc;
        __nv_bfloat16 h0 = __float2bfloat16(v0);
        __nv_bfloat16 h1 = __float2bfloat16(v1);
        g_chi[g + lane]      = h0;
        g_chi[g + lane + 32] = h1;
        g_clo[g + lane]      = __float2bfloat16(v0 - __bfloat162float(h0));
        g_clo[g + lane + 32] = __float2bfloat16(v1 - __bfloat162float(h1));
    }
}

// ---------------------------------------------------------------------------
// Launch
// ---------------------------------------------------------------------------
extern "C" void kernel_launch(void* const* d_in, const int* in_sizes, int n_in,
                              void* d_out, int out_size) {
    const float* x   = (const float*)d_in[0];
    const float* Wq  = (const float*)d_in[1];
    const float* bq  = (const float*)d_in[2];
    const float* Wk  = (const float*)d_in[3];
    const float* bk  = (const float*)d_in[4];
    const float* Wv  = (const float*)d_in[5];
    const float* bv  = (const float*)d_in[6];
    const float* Wo  = (const float*)d_in[7];
    const float* bo  = (const float*)d_in[8];
    const float* Wrf = (const float*)d_in[9];
    float* out = (float*)d_out;

    float *q, *k, *v;
    __nv_bfloat16 *xhi, *xlo, *whi, *wlo, *chi, *clo;
    cudaGetSymbolAddress((void**)&q,   g_q);
    cudaGetSymbolAddress((void**)&k,   g_k);
    cudaGetSymbolAddress((void**)&v,   g_v);
    cudaGetSymbolAddress((void**)&xhi, g_xhi);
    cudaGetSymbolAddress((void**)&xlo, g_xlo);
    cudaGetSymbolAddress((void**)&whi, g_whi);
    cudaGetSymbolAddress((void**)&wlo, g_wlo);
    cudaGetSymbolAddress((void**)&chi, g_chi);
    cudaGetSymbolAddress((void**)&clo, g_clo);

    cudaFuncSetAttribute(gemm_split, cudaFuncAttributeMaxDynamicSharedMemorySize, GEMM_SMEM);

    const size_t WN = (size_t)DIMc * DIMc;
    {
        int n4 = (int)(((size_t)Mrows * DIMc) / 4);
        split_kernel<<<(n4 + 255) / 256, 256>>>(x, xhi, xlo, n4);
        int w4 = (int)(WN / 4);
        split_kernel<<<(w4 + 255) / 256, 256>>>(Wq, whi + 0 * WN, wlo + 0 * WN, w4);
        split_kernel<<<(w4 + 255) / 256, 256>>>(Wk, whi + 1 * WN, wlo + 1 * WN, w4);
        split_kernel<<<(w4 + 255) / 256, 256>>>(Wv, whi + 2 * WN, wlo + 2 * WN, w4);
        split_kernel<<<(w4 + 255) / 256, 256>>>(Wo, whi + 3 * WN, wlo + 3 * WN, w4);
    }

    init_kernel<<<(BHc * NFc * DHc + 255) / 256, 256>>>();

    dim3 gg(DIMc / 128, Mrows / 128);
    gemm_split<<<gg, 256, GEMM_SMEM>>>(xhi, xlo, whi + 0 * WN, wlo + 0 * WN, bq, q);
    gemm_split<<<gg, 256, GEMM_SMEM>>>(xhi, xlo, whi + 1 * WN, wlo + 1 * WN, bk, k);
    gemm_split<<<gg, 256, GEMM_SMEM>>>(xhi, xlo, whi + 2 * WN, wlo + 2 * WN, bv, v);

    logits_kernel<<<dim3(Lseq / 32, BHc), 256>>>(Wrf);
    nd_kernel<<<dim3(Lseq / 256, BHc), 256>>>();
    combine_kernel<<<dim3(Lseq / 64, BHc), 256>>>();

    gemm_split<<<gg, 256, GEMM_SMEM>>>(chi, clo, whi + 3 * WN, wlo + 3 * WN, bo, out);
}

// round 5
// speedup vs baseline: 1.9168x; 1.1324x over previous
#include <cuda_runtime.h>
#include <cuda_bf16.h>
#include <math.h>
#include <stdint.h>

// Problem constants
#define Bsz  4
#define Lseq 4096
#define DIMc 1024
#define Hn   16
#define DHc  64
#define NFc  64
#define Mrows (Bsz * Lseq)          // 16384
#define BHc   (Bsz * Hn)            // 64
#define EPSf  1e-6f

// ---------------------------------------------------------------------------
// Scratch (device globals)
// ---------------------------------------------------------------------------
__device__ float g_q[(size_t)Mrows * DIMc];
__device__ float g_k[(size_t)Mrows * DIMc];
__device__ float g_v[(size_t)Mrows * DIMc];
__device__ float g_phi[(size_t)BHc * Lseq * NFc];
__device__ float g_Nt[BHc * DHc * NFc];   // transposed: [bh][d][f]
__device__ float g_D[BHc * NFc];

// bf16 split buffers
__device__ __nv_bfloat16 g_xhi[(size_t)Mrows * DIMc];
__device__ __nv_bfloat16 g_xlo[(size_t)Mrows * DIMc];
__device__ __nv_bfloat16 g_whi[4 * DIMc * DIMc];
__device__ __nv_bfloat16 g_wlo[4 * DIMc * DIMc];
__device__ __nv_bfloat16 g_chi[(size_t)Mrows * DIMc];
__device__ __nv_bfloat16 g_clo[(size_t)Mrows * DIMc];

// ---------------------------------------------------------------------------
// PTX helpers
// ---------------------------------------------------------------------------
__device__ __forceinline__ uint32_t smem_u32(const void* p) {
    uint32_t a;
    asm("{ .reg .u64 t; cvta.to.shared.u64 t, %1; cvt.u32.u64 %0, t; }" : "=r"(a) : "l"(p));
    return a;
}

#define CP16(dst, src) \
    asm volatile("cp.async.cg.shared.global [%0], [%1], 16;" :: "r"(dst), "l"(src))
#define CP_COMMIT() asm volatile("cp.async.commit_group;" ::: "memory")
#define CP_WAIT(n)  asm volatile("cp.async.wait_group %0;" :: "n"(n) : "memory")

__device__ __forceinline__ void ldsm_x4(uint32_t* r, uint32_t addr) {
    asm volatile("ldmatrix.sync.aligned.m8n8.x4.shared.b16 {%0,%1,%2,%3}, [%4];"
        : "=r"(r[0]), "=r"(r[1]), "=r"(r[2]), "=r"(r[3]) : "r"(addr));
}
__device__ __forceinline__ void mma16816(float* c, const uint32_t* a, const uint32_t* b) {
    asm volatile(
        "mma.sync.aligned.m16n8k16.row.col.f32.bf16.bf16.f32 "
        "{%0,%1,%2,%3}, {%4,%5,%6,%7}, {%8,%9}, {%0,%1,%2,%3};"
        : "+f"(c[0]), "+f"(c[1]), "+f"(c[2]), "+f"(c[3])
        : "r"(a[0]), "r"(a[1]), "r"(a[2]), "r"(a[3]), "r"(b[0]), "r"(b[1]));
}

// SMEM tile geometry: bf16 rows of 32 elems padded to 40 (80 bytes)
#define ROWB       80
#define MAT_BYTES  (128 * ROWB)      // 10240
#define STG_BYTES  (4 * MAT_BYTES)   // 40960 : Ahi | Alo | Bhi | Blo
#define NSTAGE     3
#define GEMM_SMEM  (512 + NSTAGE * STG_BYTES)
#define OFF_AHI 0
#define OFF_ALO MAT_BYTES
#define OFF_BHI (2 * MAT_BYTES)
#define OFF_BLO (3 * MAT_BYTES)

// ---------------------------------------------------------------------------
// fp32 -> bf16 hi/lo split
// ---------------------------------------------------------------------------
__global__ void split_kernel(const float* __restrict__ src,
                             __nv_bfloat16* __restrict__ hi,
                             __nv_bfloat16* __restrict__ lo, int n4) {
    int i = blockIdx.x * blockDim.x + threadIdx.x;
    if (i >= n4) return;
    float4 v = ((const float4*)src)[i];
    __nv_bfloat16 h[4], l[4];
    h[0] = __float2bfloat16(v.x); l[0] = __float2bfloat16(v.x - __bfloat162float(h[0]));
    h[1] = __float2bfloat16(v.y); l[1] = __float2bfloat16(v.y - __bfloat162float(h[1]));
    h[2] = __float2bfloat16(v.z); l[2] = __float2bfloat16(v.z - __bfloat162float(h[2]));
    h[3] = __float2bfloat16(v.w); l[3] = __float2bfloat16(v.w - __bfloat162float(h[3]));
    ((uint2*)hi)[i] = *(uint2*)h;
    ((uint2*)lo)[i] = *(uint2*)l;
}

// ---------------------------------------------------------------------------
// Init: zero N/D accumulators
// ---------------------------------------------------------------------------
__global__ void init_kernel() {
    int i = blockIdx.x * blockDim.x + threadIdx.x;
    if (i < BHc * DHc * NFc) g_Nt[i] = 0.0f;
    if (i < BHc * NFc)       g_D[i] = 0.0f;
}

// ---------------------------------------------------------------------------
// HMMA bf16-split GEMM: C[M,1024] = (Ahi+Alo)(Whi+Wlo)^T + bias
// ---------------------------------------------------------------------------
__device__ __forceinline__ void issue_chunk(
    uint32_t sbase, int t,
    const __nv_bfloat16* __restrict__ Ahi, const __nv_bfloat16* __restrict__ Alo,
    const __nv_bfloat16* __restrict__ Whi, const __nv_bfloat16* __restrict__ Wlo,
    int bm, int bn, int kOff)
{
    #pragma unroll
    for (int j = 0; j < 2; j++) {
        int idx = t + j * 256;
        int r = idx >> 2, c = idx & 3;
        uint32_t so = (uint32_t)(r * ROWB + c * 16);
        size_t ga = (size_t)(bm + r) * DIMc + kOff + c * 8;
        size_t gb = (size_t)(bn + r) * DIMc + kOff + c * 8;
        CP16(sbase + OFF_AHI + so, Ahi + ga);
        CP16(sbase + OFF_ALO + so, Alo + ga);
        CP16(sbase + OFF_BHI + so, Whi + gb);
        CP16(sbase + OFF_BLO + so, Wlo + gb);
    }
    CP_COMMIT();
}

__global__ void __launch_bounds__(256, 1) gemm_split(
    const __nv_bfloat16* __restrict__ Ahi, const __nv_bfloat16* __restrict__ Alo,
    const __nv_bfloat16* __restrict__ Whi, const __nv_bfloat16* __restrict__ Wlo,
    const float* __restrict__ bias, float* __restrict__ C)
{
    extern __shared__ __align__(16) char sm[];
    float* sbias = (float*)sm;
    uint32_t sb = smem_u32(sm) + 512;

    int t = threadIdx.x;
    int wid = t >> 5, lane = t & 31;
    int warp_m = wid >> 2, warp_n = wid & 3;
    int bm = blockIdx.y << 7;
    int bn = blockIdx.x << 7;

    if (t < 128) sbias[t] = bias[bn + t];

    float acc[4][4][4];
    #pragma unroll
    for (int mi = 0; mi < 4; mi++)
        #pragma unroll
        for (int ni = 0; ni < 4; ni++)
            #pragma unroll
            for (int e = 0; e < 4; e++) acc[mi][ni][e] = 0.0f;

    uint32_t aoff = (uint32_t)((warp_m * 64 + (lane & 15)) * ROWB + (lane >> 4) * 16);
    // x4 pair layout for B: lanes 0-7 -> (ni, k0-7), 8-15 -> (ni, k8-15),
    // 16-23 -> (ni+1, k0-7), 24-31 -> (ni+1, k8-15)
    uint32_t bpair = (uint32_t)((warp_n * 32 + (lane >> 4) * 8 + (lane & 7)) * ROWB
                                + ((lane >> 3) & 1) * 16);

    issue_chunk(sb + 0 * STG_BYTES, t, Ahi, Alo, Whi, Wlo, bm, bn, 0);
    issue_chunk(sb + 1 * STG_BYTES, t, Ahi, Alo, Whi, Wlo, bm, bn, 32);

    #pragma unroll 1
    for (int ch = 0; ch < 32; ch++) {
        CP_WAIT(1);
        __syncthreads();
        if (ch + 2 < 32)
            issue_chunk(sb + ((ch + 2) % NSTAGE) * STG_BYTES, t,
                        Ahi, Alo, Whi, Wlo, bm, bn, (ch + 2) * 32);
        uint32_t stg = sb + (ch % NSTAGE) * STG_BYTES;
        #pragma unroll
        for (int ks = 0; ks < 2; ks++) {
            uint32_t ahi[4][4], alo[4][4], bhi[4][2], blo[4][2];
            #pragma unroll
            for (int mi = 0; mi < 4; mi++) {
                uint32_t a = stg + aoff + (uint32_t)(mi * 16 * ROWB + ks * 32);
                ldsm_x4(ahi[mi], a + OFF_AHI);
                ldsm_x4(alo[mi], a + OFF_ALO);
            }
            #pragma unroll
            for (int pni = 0; pni < 4; pni += 2) {
                uint32_t tmp[4];
                uint32_t b = stg + bpair + (uint32_t)(pni * 8 * ROWB + ks * 32);
                ldsm_x4(tmp, b + OFF_BHI);
                bhi[pni][0] = tmp[0]; bhi[pni][1] = tmp[1];
                bhi[pni + 1][0] = tmp[2]; bhi[pni + 1][1] = tmp[3];
                ldsm_x4(tmp, b + OFF_BLO);
                blo[pni][0] = tmp[0]; blo[pni][1] = tmp[1];
                blo[pni + 1][0] = tmp[2]; blo[pni + 1][1] = tmp[3];
            }
            #pragma unroll
            for (int mi = 0; mi < 4; mi++)
                #pragma unroll
                for (int ni = 0; ni < 4; ni++) {
                    mma16816(acc[mi][ni], ahi[mi], bhi[ni]);
                    mma16816(acc[mi][ni], ahi[mi], blo[ni]);
                    mma16816(acc[mi][ni], alo[mi], bhi[ni]);
                }
        }
        __syncthreads();
    }

    #pragma unroll
    for (int mi = 0; mi < 4; mi++) {
        int row0 = bm + warp_m * 64 + mi * 16 + (lane >> 2);
        #pragma unroll
        for (int ni = 0; ni < 4; ni++) {
            int col = warp_n * 32 + ni * 8 + (lane & 3) * 2;
            float b0 = sbias[col], b1 = sbias[col + 1];
            float2 o0 = make_float2(acc[mi][ni][0] + b0, acc[mi][ni][1] + b1);
            float2 o1 = make_float2(acc[mi][ni][2] + b0, acc[mi][ni][3] + b1);
            *(float2*)(C + (size_t)row0 * DIMc + bn + col) = o0;
            *(float2*)(C + (size_t)(row0 + 8) * DIMc + bn + col) = o1;
        }
    }
}

// ---------------------------------------------------------------------------
// Fused feature kernel: per (bh, 64-row L-chunk):
//   E[l,f] = exp(k.W0[:,f] - 0.5||k||^2)       (no max subtraction needed)
//   phi[l,f] = softmax_f(q.W0[:,f])  -> global
//   atomicAdd: Nt[d,f] += sum_l E[l,f] V[l,d],  D[f] += sum_l E[l,f]
// SMEM: W0t (transposed, 68-pad) + k/q/v/E tiles. 256 threads.
// ---------------------------------------------------------------------------
#define W0P 68
#define FEAT_SMEM ((W0P * 64 + 4 * 64 * 64) * 4)   // 82,688 B

__global__ void __launch_bounds__(256) feature_kernel(const float* __restrict__ Wrf) {
    extern __shared__ float fs[];
    float* W0t = fs;                 // [f][d] padded rows of W0P
    float* ks  = fs + W0P * 64;      // [64][64]
    float* qs  = ks + 4096;
    float* Vs  = qs + 4096;
    float* Es  = Vs + 4096;

    int bh = blockIdx.y;
    int b = bh >> 4, h = bh & 15;
    int l0 = blockIdx.x * 64;
    int t = threadIdx.x;

    // load W0 transposed: Wrf[h][d][f] -> W0t[f*W0P + d]
    for (int e = t; e < 4096; e += 256) {
        int d = e >> 6, f = e & 63;
        W0t[f * W0P + d] = Wrf[h * 4096 + e];
    }
    // load k,q,v tiles (64 rows x 64 cols, float4)
    for (int e = t; e < 1024; e += 256) {
        int row = e >> 4, c4 = (e & 15) << 2;
        size_t g = (size_t)(b * Lseq + l0 + row) * DIMc + h * DHc + c4;
        *(float4*)(ks + row * 64 + c4) = *(const float4*)(g_k + g);
        *(float4*)(qs + row * 64 + c4) = *(const float4*)(g_q + g);
        *(float4*)(Vs + row * 64 + c4) = *(const float4*)(g_v + g);
    }
    __syncthreads();

    int warp = t >> 5, lane = t & 31;
    const float* w0p = W0t + lane * W0P;
    const float* w1p = W0t + (lane + 32) * W0P;

    #pragma unroll 1
    for (int r = 0; r < 8; r++) {
        int l = warp * 8 + r;
        const float* krow = ks + l * 64;
        const float* qrow = qs + l * 64;
        float aK0 = 0.f, aK1 = 0.f, aQ0 = 0.f, aQ1 = 0.f, kk = 0.f;
        #pragma unroll
        for (int d = 0; d < 64; d += 4) {
            float4 kv = *(const float4*)(krow + d);
            float4 qv = *(const float4*)(qrow + d);
            float4 w0 = *(const float4*)(w0p + d);
            float4 w1 = *(const float4*)(w1p + d);
            aK0 = fmaf(kv.x, w0.x, aK0); aK0 = fmaf(kv.y, w0.y, aK0);
            aK0 = fmaf(kv.z, w0.z, aK0); aK0 = fmaf(kv.w, w0.w, aK0);
            aK1 = fmaf(kv.x, w1.x, aK1); aK1 = fmaf(kv.y, w1.y, aK1);
            aK1 = fmaf(kv.z, w1.z, aK1); aK1 = fmaf(kv.w, w1.w, aK1);
            aQ0 = fmaf(qv.x, w0.x, aQ0); aQ0 = fmaf(qv.y, w0.y, aQ0);
            aQ0 = fmaf(qv.z, w0.z, aQ0); aQ0 = fmaf(qv.w, w0.w, aQ0);
            aQ1 = fmaf(qv.x, w1.x, aQ1); aQ1 = fmaf(qv.y, w1.y, aQ1);
            aQ1 = fmaf(qv.z, w1.z, aQ1); aQ1 = fmaf(qv.w, w1.w, aQ1);
            kk  = fmaf(kv.x, kv.x, kk);  kk  = fmaf(kv.y, kv.y, kk);
            kk  = fmaf(kv.z, kv.z, kk);  kk  = fmaf(kv.w, kv.w, kk);
        }
        float hk = 0.5f * kk;
        Es[l * 64 + lane]      = __expf(aK0 - hk);
        Es[l * 64 + lane + 32] = __expf(aK1 - hk);

        // per-position softmax over 64 features (no max: |logit| << 88)
        float e0 = __expf(aQ0), e1 = __expf(aQ1);
        float s = e0 + e1;
        #pragma unroll
        for (int o = 16; o > 0; o >>= 1)
            s += __shfl_xor_sync(0xffffffffu, s, o);
        float inv = 1.0f / s;
        size_t base = ((size_t)bh * Lseq + l0 + l) * NFc;
        g_phi[base + lane]      = e0 * inv;
        g_phi[base + lane + 32] = e1 * inv;
    }
    __syncthreads();

    // Phase B: Nt[d][f] += E^T V ; D[f] += colsum(E)
    int tf = (t >> 4) << 2;   // feature group
    int td = (t & 15) << 2;   // d group
    float acc[4][4];
    #pragma unroll
    for (int i = 0; i < 4; i++)
        #pragma unroll
        for (int j = 0; j < 4; j++) acc[i][j] = 0.0f;
    float dacc[4] = {0.f, 0.f, 0.f, 0.f};

    #pragma unroll 4
    for (int l = 0; l < 64; l++) {
        float4 a  = *(const float4*)(Es + l * 64 + tf);
        float4 b4 = *(const float4*)(Vs + l * 64 + td);
        float av[4] = {a.x, a.y, a.z, a.w};
        float bv[4] = {b4.x, b4.y, b4.z, b4.w};
        #pragma unroll
        for (int i = 0; i < 4; i++)
            #pragma unroll
            for (int j = 0; j < 4; j++)
                acc[i][j] = fmaf(av[i], bv[j], acc[i][j]);
        if (td == 0) {
            #pragma unroll
            for (int i = 0; i < 4; i++) dacc[i] += av[i];
        }
    }

    #pragma unroll
    for (int i = 0; i < 4; i++)
        #pragma unroll
        for (int j = 0; j < 4; j++)
            atomicAdd(&g_Nt[bh * (DHc * NFc) + (td + j) * NFc + tf + i], acc[i][j]);
    if (td == 0) {
        #pragma unroll
        for (int i = 0; i < 4; i++)
            atomicAdd(&g_D[bh * NFc + tf + i], dacc[i]);
    }
}

// ---------------------------------------------------------------------------
// Combine: ctx_hi/lo[b,l,h*64+d] = (phi . Nt[d,:]) / (phi . D + S*EPS)
// Nt rows padded to 68 in SMEM for conflict-free per-lane float4 reads.
// ---------------------------------------------------------------------------
__global__ void __launch_bounds__(256) combine_kernel() {
    int bh = blockIdx.y;
    int b = bh >> 4, h = bh & 15;
    int l0 = blockIdx.x * 64;

    __shared__ float Nts[64 * W0P];
    __shared__ float Ds[NFc];
    __shared__ float sSE;

    int t = threadIdx.x;
    for (int e = t; e < 4096; e += 256) {
        int d = e >> 6, f = e & 63;
        Nts[d * W0P + f] = g_Nt[bh * (DHc * NFc) + e];
    }
    if (t < NFc) Ds[t] = g_D[bh * NFc + t];
    __syncthreads();
    if (t == 0) {
        float s = 0.f;
        #pragma unroll
        for (int f = 0; f < NFc; f++) s += Ds[f];
        sSE = s * EPSf;
    }
    __syncthreads();

    int warp = t >> 5, lane = t & 31;
    const float* n0p = Nts + lane * W0P;
    const float* n1p = Nts + (lane + 32) * W0P;

    #pragma unroll 1
    for (int r = 0; r < 8; r++) {
        int l = l0 + warp * 8 + r;
        const float4* pr = (const float4*)(g_phi + ((size_t)bh * Lseq + l) * NFc);
        float num0 = 0.f, num1 = 0.f, den = 0.f;
        #pragma unroll
        for (int j = 0; j < 16; j++) {
            float4 p  = pr[j];
            float4 n0 = *(const float4*)(n0p + j * 4);
            float4 n1 = *(const float4*)(n1p + j * 4);
            float4 dd = *(const float4*)(Ds + j * 4);
            num0 = fmaf(p.x, n0.x, num0); num0 = fmaf(p.y, n0.y, num0);
            num0 = fmaf(p.z, n0.z, num0); num0 = fmaf(p.w, n0.w, num0);
            num1 = fmaf(p.x, n1.x, num1); num1 = fmaf(p.y, n1.y, num1);
            num1 = fmaf(p.z, n1.z, num1); num1 = fmaf(p.w, n1.w, num1);
            den  = fmaf(p.x, dd.x, den);  den  = fmaf(p.y, dd.y, den);
            den  = fmaf(p.z, dd.z, den);  den  = fmaf(p.w, dd.w, den);
        }
        float invd = 1.0f / (den + sSE);
        float v0 = num0 * invd;
        float v1 = num1 * invd;
        size_t g = (size_t)(b * Lseq + l) * DIMc + h * DHc;
        __nv_bfloat16 h0 = __float2bfloat16(v0);
        __nv_bfloat16 h1 = __float2bfloat16(v1);
        g_chi[g + lane]      = h0;
        g_chi[g + lane + 32] = h1;
        g_clo[g + lane]      = __float2bfloat16(v0 - __bfloat162float(h0));
        g_clo[g + lane + 32] = __float2bfloat16(v1 - __bfloat162float(h1));
    }
}

// ---------------------------------------------------------------------------
// Launch
// ---------------------------------------------------------------------------
extern "C" void kernel_launch(void* const* d_in, const int* in_sizes, int n_in,
                              void* d_out, int out_size) {
    const float* x   = (const float*)d_in[0];
    const float* Wq  = (const float*)d_in[1];
    const float* bq  = (const float*)d_in[2];
    const float* Wk  = (const float*)d_in[3];
    const float* bk  = (const float*)d_in[4];
    const float* Wv  = (const float*)d_in[5];
    const float* bv  = (const float*)d_in[6];
    const float* Wo  = (const float*)d_in[7];
    const float* bo  = (const float*)d_in[8];
    const float* Wrf = (const float*)d_in[9];
    float* out = (float*)d_out;

    float *q, *k, *v;
    __nv_bfloat16 *xhi, *xlo, *whi, *wlo, *chi, *clo;
    cudaGetSymbolAddress((void**)&q,   g_q);
    cudaGetSymbolAddress((void**)&k,   g_k);
    cudaGetSymbolAddress((void**)&v,   g_v);
    cudaGetSymbolAddress((void**)&xhi, g_xhi);
    cudaGetSymbolAddress((void**)&xlo, g_xlo);
    cudaGetSymbolAddress((void**)&whi, g_whi);
    cudaGetSymbolAddress((void**)&wlo, g_wlo);
    cudaGetSymbolAddress((void**)&chi, g_chi);
    cudaGetSymbolAddress((void**)&clo, g_clo);

    cudaFuncSetAttribute(gemm_split, cudaFuncAttributeMaxDynamicSharedMemorySize, GEMM_SMEM);
    cudaFuncSetAttribute(feature_kernel, cudaFuncAttributeMaxDynamicSharedMemorySize, FEAT_SMEM);

    const size_t WN = (size_t)DIMc * DIMc;
    {
        int n4 = (int)(((size_t)Mrows * DIMc) / 4);
        split_kernel<<<(n4 + 255) / 256, 256>>>(x, xhi, xlo, n4);
        int w4 = (int)(WN / 4);
        split_kernel<<<(w4 + 255) / 256, 256>>>(Wq, whi + 0 * WN, wlo + 0 * WN, w4);
        split_kernel<<<(w4 + 255) / 256, 256>>>(Wk, whi + 1 * WN, wlo + 1 * WN, w4);
        split_kernel<<<(w4 + 255) / 256, 256>>>(Wv, whi + 2 * WN, wlo + 2 * WN, w4);
        split_kernel<<<(w4 + 255) / 256, 256>>>(Wo, whi + 3 * WN, wlo + 3 * WN, w4);
    }

    init_kernel<<<(BHc * DHc * NFc + 255) / 256, 256>>>();

    dim3 gg(DIMc / 128, Mrows / 128);
    gemm_split<<<gg, 256, GEMM_SMEM>>>(xhi, xlo, whi + 0 * WN, wlo + 0 * WN, bq, q);
    gemm_split<<<gg, 256, GEMM_SMEM>>>(xhi, xlo, whi + 1 * WN, wlo + 1 * WN, bk, k);
    gemm_split<<<gg, 256, GEMM_SMEM>>>(xhi, xlo, whi + 2 * WN, wlo + 2 * WN, bv, v);

    feature_kernel<<<dim3(Lseq / 64, BHc), 256, FEAT_SMEM>>>(Wrf);
    combine_kernel<<<dim3(Lseq / 64, BHc), 256>>>();

    gemm_split<<<gg, 256, GEMM_SMEM>>>(chi, clo, whi + 3 * WN, wlo + 3 * WN, bo, out);
}

// round 6
// speedup vs baseline: 1.9486x; 1.0166x over previous
#include <cuda_runtime.h>
#include <cuda_bf16.h>
#include <math.h>
#include <stdint.h>

// Problem constants
#define Bsz  4
#define Lseq 4096
#define DIMc 1024
#define Hn   16
#define DHc  64
#define NFc  64
#define Mrows (Bsz * Lseq)          // 16384
#define BHc   (Bsz * Hn)            // 64
#define EPSf  1e-6f

// ---------------------------------------------------------------------------
// Scratch (device globals)
// ---------------------------------------------------------------------------
__device__ float g_q[(size_t)Mrows * DIMc];
__device__ float g_k[(size_t)Mrows * DIMc];
__device__ float g_v[(size_t)Mrows * DIMc];
__device__ float g_phi[(size_t)BHc * Lseq * NFc];
__device__ float g_Nt[BHc * DHc * NFc];   // transposed: [bh][d][f]
__device__ float g_D[BHc * NFc];

// bf16 split buffers
__device__ __nv_bfloat16 g_xhi[(size_t)Mrows * DIMc];
__device__ __nv_bfloat16 g_xlo[(size_t)Mrows * DIMc];
__device__ __nv_bfloat16 g_whi[4 * DIMc * DIMc];
__device__ __nv_bfloat16 g_wlo[4 * DIMc * DIMc];
__device__ __nv_bfloat16 g_chi[(size_t)Mrows * DIMc];
__device__ __nv_bfloat16 g_clo[(size_t)Mrows * DIMc];

// ---------------------------------------------------------------------------
// PTX helpers
// ---------------------------------------------------------------------------
__device__ __forceinline__ uint32_t smem_u32(const void* p) {
    uint32_t a;
    asm("{ .reg .u64 t; cvta.to.shared.u64 t, %1; cvt.u32.u64 %0, t; }" : "=r"(a) : "l"(p));
    return a;
}

#define CP16(dst, src) \
    asm volatile("cp.async.cg.shared.global [%0], [%1], 16;" :: "r"(dst), "l"(src))
#define CP_COMMIT() asm volatile("cp.async.commit_group;" ::: "memory")
#define CP_WAIT(n)  asm volatile("cp.async.wait_group %0;" :: "n"(n) : "memory")

__device__ __forceinline__ void ldsm_x4(uint32_t* r, uint32_t addr) {
    asm volatile("ldmatrix.sync.aligned.m8n8.x4.shared.b16 {%0,%1,%2,%3}, [%4];"
        : "=r"(r[0]), "=r"(r[1]), "=r"(r[2]), "=r"(r[3]) : "r"(addr));
}
__device__ __forceinline__ void mma16816(float* c, const uint32_t* a, const uint32_t* b) {
    asm volatile(
        "mma.sync.aligned.m16n8k16.row.col.f32.bf16.bf16.f32 "
        "{%0,%1,%2,%3}, {%4,%5,%6,%7}, {%8,%9}, {%0,%1,%2,%3};"
        : "+f"(c[0]), "+f"(c[1]), "+f"(c[2]), "+f"(c[3])
        : "r"(a[0]), "r"(a[1]), "r"(a[2]), "r"(a[3]), "r"(b[0]), "r"(b[1]));
}

// SMEM tile geometry: bf16 rows of 32 elems padded to 40 (80 bytes) -> ldmatrix
// octets hit distinct banks (stride 20 banks, gcd(20,32) pattern covers all 32).
#define ROWB       80
#define A_BYTES    (128 * ROWB)          // 10240
#define B_BYTES    (256 * ROWB)          // 20480
#define STG_BYTES  (2 * A_BYTES + 2 * B_BYTES)   // 61440 : Ahi|Alo|Bhi|Blo
#define NSTAGE     3
#define GEMM_SMEM  (1024 + NSTAGE * STG_BYTES)   // 185344
#define OFF_AHI 0
#define OFF_ALO A_BYTES
#define OFF_BHI (2 * A_BYTES)
#define OFF_BLO (2 * A_BYTES + B_BYTES)

struct GemmArgs {
    const __nv_bfloat16* whi[3];
    const __nv_bfloat16* wlo[3];
    const float* bias[3];
    float* C[3];
};

// ---------------------------------------------------------------------------
// fp32 -> bf16 hi/lo split
// ---------------------------------------------------------------------------
__global__ void split_kernel(const float* __restrict__ src,
                             __nv_bfloat16* __restrict__ hi,
                             __nv_bfloat16* __restrict__ lo, int n4) {
    int i = blockIdx.x * blockDim.x + threadIdx.x;
    if (i >= n4) return;
    float4 v = ((const float4*)src)[i];
    __nv_bfloat16 h[4], l[4];
    h[0] = __float2bfloat16(v.x); l[0] = __float2bfloat16(v.x - __bfloat162float(h[0]));
    h[1] = __float2bfloat16(v.y); l[1] = __float2bfloat16(v.y - __bfloat162float(h[1]));
    h[2] = __float2bfloat16(v.z); l[2] = __float2bfloat16(v.z - __bfloat162float(h[2]));
    h[3] = __float2bfloat16(v.w); l[3] = __float2bfloat16(v.w - __bfloat162float(h[3]));
    ((uint2*)hi)[i] = *(uint2*)h;
    ((uint2*)lo)[i] = *(uint2*)l;
}

// ---------------------------------------------------------------------------
// Init: zero N/D accumulators
// ---------------------------------------------------------------------------
__global__ void init_kernel() {
    int i = blockIdx.x * blockDim.x + threadIdx.x;
    if (i < BHc * DHc * NFc) g_Nt[i] = 0.0f;
    if (i < BHc * NFc)       g_D[i] = 0.0f;
}

// ---------------------------------------------------------------------------
// HMMA bf16-split GEMM: 128(M) x 256(N) tile, BK=32, 3-stage cp.async.
// grid.x = 4*nW (4 N-blocks of 256 per weight); weight selected by bx>>2.
// 8 warps in 2x4: warp tile 64x64 (4 m16 x 8 n8), 128 accum regs/thread.
// ---------------------------------------------------------------------------
__device__ __forceinline__ void issue_chunk2(
    uint32_t sbase, int t,
    const __nv_bfloat16* __restrict__ Ahi, const __nv_bfloat16* __restrict__ Alo,
    const __nv_bfloat16* __restrict__ Whi, const __nv_bfloat16* __restrict__ Wlo,
    int bm, int nLoc, int kOff)
{
    // 3072 16B segments: A-hi 512, A-lo 512, B-hi 1024, B-lo 1024
    #pragma unroll
    for (int j = 0; j < 12; j++) {
        int idx = t + j * 256;
        int r = idx >> 2, c = idx & 3;
        uint32_t so;
        const __nv_bfloat16* src;
        if (r < 256) {        // A region: hi rows 0-127, lo rows 128-255
            int rr = r & 127;
            so = (uint32_t)((r < 128 ? OFF_AHI : OFF_ALO) + rr * ROWB + c * 16);
            src = (r < 128 ? Ahi : Alo) + (size_t)(bm + rr) * DIMc + kOff + c * 8;
        } else {              // B region: hi rows 0-255, lo rows 256-511
            int rb = r - 256;
            int rr = rb & 255;
            so = (uint32_t)((rb < 256 ? OFF_BHI : OFF_BLO) + rr * ROWB + c * 16);
            src = (rb < 256 ? Whi : Wlo) + (size_t)(nLoc + rr) * DIMc + kOff + c * 8;
        }
        CP16(sbase + so, src);
    }
    CP_COMMIT();
}

__global__ void __launch_bounds__(256, 1) gemm_split(
    const __nv_bfloat16* __restrict__ Ahi, const __nv_bfloat16* __restrict__ Alo,
    GemmArgs args)
{
    extern __shared__ __align__(16) char sm[];
    float* sbias = (float*)sm;
    uint32_t sb = smem_u32(sm) + 1024;

    int t = threadIdx.x;
    int wid = t >> 5, lane = t & 31;
    int warp_m = wid >> 2, warp_n = wid & 3;
    int bm = blockIdx.y << 7;
    int wsel = blockIdx.x >> 2;
    int nLoc = (blockIdx.x & 3) << 8;

    const __nv_bfloat16* Whi = args.whi[wsel];
    const __nv_bfloat16* Wlo = args.wlo[wsel];
    float* C = args.C[wsel];

    if (t < 256) sbias[t] = args.bias[wsel][nLoc + t];

    float acc[4][8][4];
    #pragma unroll
    for (int mi = 0; mi < 4; mi++)
        #pragma unroll
        for (int ni = 0; ni < 8; ni++)
            #pragma unroll
            for (int e = 0; e < 4; e++) acc[mi][ni][e] = 0.0f;

    uint32_t aoff = (uint32_t)((warp_m * 64 + (lane & 15)) * ROWB + (lane >> 4) * 16);
    uint32_t bpair = (uint32_t)((warp_n * 64 + (lane >> 4) * 8 + (lane & 7)) * ROWB
                                + ((lane >> 3) & 1) * 16);

    issue_chunk2(sb + 0 * STG_BYTES, t, Ahi, Alo, Whi, Wlo, bm, nLoc, 0);
    issue_chunk2(sb + 1 * STG_BYTES, t, Ahi, Alo, Whi, Wlo, bm, nLoc, 32);

    #pragma unroll 1
    for (int ch = 0; ch < 32; ch++) {
        CP_WAIT(1);
        __syncthreads();
        if (ch + 2 < 32)
            issue_chunk2(sb + ((ch + 2) % NSTAGE) * STG_BYTES, t,
                         Ahi, Alo, Whi, Wlo, bm, nLoc, (ch + 2) * 32);
        uint32_t stg = sb + (ch % NSTAGE) * STG_BYTES;
        #pragma unroll
        for (int ks = 0; ks < 2; ks++) {
            uint32_t ahi[4][4], alo[4][4], bhi[8][2], blo[8][2];
            #pragma unroll
            for (int mi = 0; mi < 4; mi++) {
                uint32_t a = stg + aoff + (uint32_t)(mi * 16 * ROWB + ks * 32);
                ldsm_x4(ahi[mi], a + OFF_AHI);
                ldsm_x4(alo[mi], a + OFF_ALO);
            }
            #pragma unroll
            for (int pni = 0; pni < 8; pni += 2) {
                uint32_t tmp[4];
                uint32_t b = stg + bpair + (uint32_t)(pni * 8 * ROWB + ks * 32);
                ldsm_x4(tmp, b + OFF_BHI);
                bhi[pni][0] = tmp[0]; bhi[pni][1] = tmp[1];
                bhi[pni + 1][0] = tmp[2]; bhi[pni + 1][1] = tmp[3];
                ldsm_x4(tmp, b + OFF_BLO);
                blo[pni][0] = tmp[0]; blo[pni][1] = tmp[1];
                blo[pni + 1][0] = tmp[2]; blo[pni + 1][1] = tmp[3];
            }
            #pragma unroll
            for (int mi = 0; mi < 4; mi++)
                #pragma unroll
                for (int ni = 0; ni < 8; ni++) {
                    mma16816(acc[mi][ni], ahi[mi], bhi[ni]);
                    mma16816(acc[mi][ni], ahi[mi], blo[ni]);
                    mma16816(acc[mi][ni], alo[mi], bhi[ni]);
                }
        }
        __syncthreads();
    }

    // epilogue
    #pragma unroll
    for (int mi = 0; mi < 4; mi++) {
        int row0 = bm + warp_m * 64 + mi * 16 + (lane >> 2);
        #pragma unroll
        for (int ni = 0; ni < 8; ni++) {
            int col = warp_n * 64 + ni * 8 + (lane & 3) * 2;
            float b0 = sbias[col], b1 = sbias[col + 1];
            float2 o0 = make_float2(acc[mi][ni][0] + b0, acc[mi][ni][1] + b1);
            float2 o1 = make_float2(acc[mi][ni][2] + b0, acc[mi][ni][3] + b1);
            *(float2*)(C + (size_t)row0 * DIMc + nLoc + col) = o0;
            *(float2*)(C + (size_t)(row0 + 8) * DIMc + nLoc + col) = o1;
        }
    }
}

// ---------------------------------------------------------------------------
// Fused feature kernel (unchanged from R5)
// ---------------------------------------------------------------------------
#define W0P 68
#define FEAT_SMEM ((W0P * 64 + 4 * 64 * 64) * 4)   // 82,688 B

__global__ void __launch_bounds__(256) feature_kernel(const float* __restrict__ Wrf) {
    extern __shared__ float fs[];
    float* W0t = fs;
    float* ks  = fs + W0P * 64;
    float* qs  = ks + 4096;
    float* Vs  = qs + 4096;
    float* Es  = Vs + 4096;

    int bh = blockIdx.y;
    int b = bh >> 4, h = bh & 15;
    int l0 = blockIdx.x * 64;
    int t = threadIdx.x;

    for (int e = t; e < 4096; e += 256) {
        int d = e >> 6, f = e & 63;
        W0t[f * W0P + d] = Wrf[h * 4096 + e];
    }
    for (int e = t; e < 1024; e += 256) {
        int row = e >> 4, c4 = (e & 15) << 2;
        size_t g = (size_t)(b * Lseq + l0 + row) * DIMc + h * DHc + c4;
        *(float4*)(ks + row * 64 + c4) = *(const float4*)(g_k + g);
        *(float4*)(qs + row * 64 + c4) = *(const float4*)(g_q + g);
        *(float4*)(Vs + row * 64 + c4) = *(const float4*)(g_v + g);
    }
    __syncthreads();

    int warp = t >> 5, lane = t & 31;
    const float* w0p = W0t + lane * W0P;
    const float* w1p = W0t + (lane + 32) * W0P;

    #pragma unroll 1
    for (int r = 0; r < 8; r++) {
        int l = warp * 8 + r;
        const float* krow = ks + l * 64;
        const float* qrow = qs + l * 64;
        float aK0 = 0.f, aK1 = 0.f, aQ0 = 0.f, aQ1 = 0.f, kk = 0.f;
        #pragma unroll
        for (int d = 0; d < 64; d += 4) {
            float4 kv = *(const float4*)(krow + d);
            float4 qv = *(const float4*)(qrow + d);
            float4 w0 = *(const float4*)(w0p + d);
            float4 w1 = *(const float4*)(w1p + d);
            aK0 = fmaf(kv.x, w0.x, aK0); aK0 = fmaf(kv.y, w0.y, aK0);
            aK0 = fmaf(kv.z, w0.z, aK0); aK0 = fmaf(kv.w, w0.w, aK0);
            aK1 = fmaf(kv.x, w1.x, aK1); aK1 = fmaf(kv.y, w1.y, aK1);
            aK1 = fmaf(kv.z, w1.z, aK1); aK1 = fmaf(kv.w, w1.w, aK1);
            aQ0 = fmaf(qv.x, w0.x, aQ0); aQ0 = fmaf(qv.y, w0.y, aQ0);
            aQ0 = fmaf(qv.z, w0.z, aQ0); aQ0 = fmaf(qv.w, w0.w, aQ0);
            aQ1 = fmaf(qv.x, w1.x, aQ1); aQ1 = fmaf(qv.y, w1.y, aQ1);
            aQ1 = fmaf(qv.z, w1.z, aQ1); aQ1 = fmaf(qv.w, w1.w, aQ1);
            kk  = fmaf(kv.x, kv.x, kk);  kk  = fmaf(kv.y, kv.y, kk);
            kk  = fmaf(kv.z, kv.z, kk);  kk  = fmaf(kv.w, kv.w, kk);
        }
        float hk = 0.5f * kk;
        Es[l * 64 + lane]      = __expf(aK0 - hk);
        Es[l * 64 + lane + 32] = __expf(aK1 - hk);

        float e0 = __expf(aQ0), e1 = __expf(aQ1);
        float s = e0 + e1;
        #pragma unroll
        for (int o = 16; o > 0; o >>= 1)
            s += __shfl_xor_sync(0xffffffffu, s, o);
        float inv = 1.0f / s;
        size_t base = ((size_t)bh * Lseq + l0 + l) * NFc;
        g_phi[base + lane]      = e0 * inv;
        g_phi[base + lane + 32] = e1 * inv;
    }
    __syncthreads();

    int tf = (t >> 4) << 2;
    int td = (t & 15) << 2;
    float acc[4][4];
    #pragma unroll
    for (int i = 0; i < 4; i++)
        #pragma unroll
        for (int j = 0; j < 4; j++) acc[i][j] = 0.0f;
    float dacc[4] = {0.f, 0.f, 0.f, 0.f};

    #pragma unroll 4
    for (int l = 0; l < 64; l++) {
        float4 a  = *(const float4*)(Es + l * 64 + tf);
        float4 b4 = *(const float4*)(Vs + l * 64 + td);
        float av[4] = {a.x, a.y, a.z, a.w};
        float bv[4] = {b4.x, b4.y, b4.z, b4.w};
        #pragma unroll
        for (int i = 0; i < 4; i++)
            #pragma unroll
            for (int j = 0; j < 4; j++)
                acc[i][j] = fmaf(av[i], bv[j], acc[i][j]);
        if (td == 0) {
            #pragma unroll
            for (int i = 0; i < 4; i++) dacc[i] += av[i];
        }
    }

    #pragma unroll
    for (int i = 0; i < 4; i++)
        #pragma unroll
        for (int j = 0; j < 4; j++)
            atomicAdd(&g_Nt[bh * (DHc * NFc) + (td + j) * NFc + tf + i], acc[i][j]);
    if (td == 0) {
        #pragma unroll
        for (int i = 0; i < 4; i++)
            atomicAdd(&g_D[bh * NFc + tf + i], dacc[i]);
    }
}

// ---------------------------------------------------------------------------
// Combine (unchanged from R5)
// ---------------------------------------------------------------------------
__global__ void __launch_bounds__(256) combine_kernel() {
    int bh = blockIdx.y;
    int b = bh >> 4, h = bh & 15;
    int l0 = blockIdx.x * 64;

    __shared__ float Nts[64 * W0P];
    __shared__ float Ds[NFc];
    __shared__ float sSE;

    int t = threadIdx.x;
    for (int e = t; e < 4096; e += 256) {
        int d = e >> 6, f = e & 63;
        Nts[d * W0P + f] = g_Nt[bh * (DHc * NFc) + e];
    }
    if (t < NFc) Ds[t] = g_D[bh * NFc + t];
    __syncthreads();
    if (t == 0) {
        float s = 0.f;
        #pragma unroll
        for (int f = 0; f < NFc; f++) s += Ds[f];
        sSE = s * EPSf;
    }
    __syncthreads();

    int warp = t >> 5, lane = t & 31;
    const float* n0p = Nts + lane * W0P;
    const float* n1p = Nts + (lane + 32) * W0P;

    #pragma unroll 1
    for (int r = 0; r < 8; r++) {
        int l = l0 + warp * 8 + r;
        const float4* pr = (const float4*)(g_phi + ((size_t)bh * Lseq + l) * NFc);
        float num0 = 0.f, num1 = 0.f, den = 0.f;
        #pragma unroll
        for (int j = 0; j < 16; j++) {
            float4 p  = pr[j];
            float4 n0 = *(const float4*)(n0p + j * 4);
            float4 n1 = *(const float4*)(n1p + j * 4);
            float4 dd = *(const float4*)(Ds + j * 4);
            num0 = fmaf(p.x, n0.x, num0); num0 = fmaf(p.y, n0.y, num0);
            num0 = fmaf(p.z, n0.z, num0); num0 = fmaf(p.w, n0.w, num0);
            num1 = fmaf(p.x, n1.x, num1); num1 = fmaf(p.y, n1.y, num1);
            num1 = fmaf(p.z, n1.z, num1); num1 = fmaf(p.w, n1.w, num1);
            den  = fmaf(p.x, dd.x, den);  den  = fmaf(p.y, dd.y, den);
            den  = fmaf(p.z, dd.z, den);  den  = fmaf(p.w, dd.w, den);
        }
        float invd = 1.0f / (den + sSE);
        float v0 = num0 * invd;
        float v1 = num1 * invd;
        size_t g = (size_t)(b * Lseq + l) * DIMc + h * DHc;
        __nv_bfloat16 h0 = __float2bfloat16(v0);
        __nv_bfloat16 h1 = __float2bfloat16(v1);
        g_chi[g + lane]      = h0;
        g_chi[g + lane + 32] = h1;
        g_clo[g + lane]      = __float2bfloat16(v0 - __bfloat162float(h0));
        g_clo[g + lane + 32] = __float2bfloat16(v1 - __bfloat162float(h1));
    }
}

// ---------------------------------------------------------------------------
// Launch
// ---------------------------------------------------------------------------
extern "C" void kernel_launch(void* const* d_in, const int* in_sizes, int n_in,
                              void* d_out, int out_size) {
    const float* x   = (const float*)d_in[0];
    const float* Wq  = (const float*)d_in[1];
    const float* bq  = (const float*)d_in[2];
    const float* Wk  = (const float*)d_in[3];
    const float* bk  = (const float*)d_in[4];
    const float* Wv  = (const float*)d_in[5];
    const float* bv  = (const float*)d_in[6];
    const float* Wo  = (const float*)d_in[7];
    const float* bo  = (const float*)d_in[8];
    const float* Wrf = (const float*)d_in[9];
    float* out = (float*)d_out;

    float *q, *k, *v;
    __nv_bfloat16 *xhi, *xlo, *whi, *wlo, *chi, *clo;
    cudaGetSymbolAddress((void**)&q,   g_q);
    cudaGetSymbolAddress((void**)&k,   g_k);
    cudaGetSymbolAddress((void**)&v,   g_v);
    cudaGetSymbolAddress((void**)&xhi, g_xhi);
    cudaGetSymbolAddress((void**)&xlo, g_xlo);
    cudaGetSymbolAddress((void**)&whi, g_whi);
    cudaGetSymbolAddress((void**)&wlo, g_wlo);
    cudaGetSymbolAddress((void**)&chi, g_chi);
    cudaGetSymbolAddress((void**)&clo, g_clo);

    cudaFuncSetAttribute(gemm_split, cudaFuncAttributeMaxDynamicSharedMemorySize, GEMM_SMEM);
    cudaFuncSetAttribute(feature_kernel, cudaFuncAttributeMaxDynamicSharedMemorySize, FEAT_SMEM);

    const size_t WN = (size_t)DIMc * DIMc;
    {
        int n4 = (int)(((size_t)Mrows * DIMc) / 4);
        split_kernel<<<(n4 + 255) / 256, 256>>>(x, xhi, xlo, n4);
        int w4 = (int)(WN / 4);
        split_kernel<<<(w4 + 255) / 256, 256>>>(Wq, whi + 0 * WN, wlo + 0 * WN, w4);
        split_kernel<<<(w4 + 255) / 256, 256>>>(Wk, whi + 1 * WN, wlo + 1 * WN, w4);
        split_kernel<<<(w4 + 255) / 256, 256>>>(Wv, whi + 2 * WN, wlo + 2 * WN, w4);
        split_kernel<<<(w4 + 255) / 256, 256>>>(Wo, whi + 3 * WN, wlo + 3 * WN, w4);
    }

    init_kernel<<<(BHc * DHc * NFc + 255) / 256, 256>>>();

    // Fused QKV GEMM: grid.x = 3 weights x 4 N-blocks
    {
        GemmArgs a;
        a.whi[0] = whi + 0 * WN; a.whi[1] = whi + 1 * WN; a.whi[2] = whi + 2 * WN;
        a.wlo[0] = wlo + 0 * WN; a.wlo[1] = wlo + 1 * WN; a.wlo[2] = wlo + 2 * WN;
        a.bias[0] = bq; a.bias[1] = bk; a.bias[2] = bv;
        a.C[0] = q; a.C[1] = k; a.C[2] = v;
        gemm_split<<<dim3(12, Mrows / 128), 256, GEMM_SMEM>>>(xhi, xlo, a);
    }

    feature_kernel<<<dim3(Lseq / 64, BHc), 256, FEAT_SMEM>>>(Wrf);
    combine_kernel<<<dim3(Lseq / 64, BHc), 256>>>();

    // Output GEMM
    {
        GemmArgs a;
        a.whi[0] = a.whi[1] = a.whi[2] = whi + 3 * WN;
        a.wlo[0] = a.wlo[1] = a.wlo[2] = wlo + 3 * WN;
        a.bias[0] = a.bias[1] = a.bias[2] = bo;
        a.C[0] = a.C[1] = a.C[2] = out;
        gemm_split<<<dim3(4, Mrows / 128), 256, GEMM_SMEM>>>(chi, clo, a);
    }
}